// round 3
// baseline (speedup 1.0000x reference)
#include <cuda_runtime.h>

#define EPS 1e-8f

namespace {
constexpr int B = 256;
constexpr int S = 24;
constexpr int D = 256;
constexpr int N = 8192;
}

// ---------------------------------------------------------------------------
// Fused kernel: grid = (S+1, B), 1024 threads.
//   blockIdx.x == i in [0,S): one output row (b,i) of new_patch_attn.
//   blockIdx.x == S:          new_slots row-block + slot_nums for batch b.
// ---------------------------------------------------------------------------
__global__ void __launch_bounds__(1024) fused_kernel(
    const float* __restrict__ slots,     // [B,S,D]
    const float* __restrict__ pa,        // [B,S,N]
    const int* __restrict__ clusters,    // [B,S] int32
    float* __restrict__ out_slots,       // [B,S,D]
    float* __restrict__ out_attn,        // [B,S,N]
    float* __restrict__ out_nums)        // [B]
{
    const int i = blockIdx.x;   // 0..S  (S = slots path)
    const int b = blockIdx.y;
    const int t = threadIdx.x;

    __shared__ int cl[S];
    if (t < S) cl[t] = clusters[b * S + t];
    __syncthreads();

    // ------------------------------------------------------------------
    // Slots path (one light block per batch)
    // ------------------------------------------------------------------
    if (i == S) {
        if (t < D) {
            const int d = t;
            float sv[S];
            const float* sb = slots + (size_t)b * S * D + d;
            #pragma unroll
            for (int j = 0; j < S; j++) sv[j] = sb[j * D];

            float* ob = out_slots + (size_t)b * S * D + d;
            #pragma unroll
            for (int ii = 0; ii < S; ii++) {
                float acc = 0.0f;
                int c = 0;
                #pragma unroll
                for (int j = 0; j < S; j++) {
                    bool hit = (cl[j] == ii);
                    if (hit) acc += sv[j];
                    c += hit;
                }
                ob[ii * D] = acc / ((float)c + EPS);
            }
            if (d == 0) {
                int n = 0;
                #pragma unroll
                for (int ii = 0; ii < S; ii++) {
                    int c = 0;
                    #pragma unroll
                    for (int j = 0; j < S; j++) c += (cl[j] == ii);
                    n += (c > 0);
                }
                out_nums[b] = (float)n;
            }
        }
        return;
    }

    // ------------------------------------------------------------------
    // Attn path: segment-sum + EPS + row-normalize for output row (b,i)
    // ------------------------------------------------------------------
    __shared__ int list[S];
    __shared__ int mcnt;
    __shared__ float wsum[32];

    if (t == 0) {
        int m = 0;
        #pragma unroll
        for (int j = 0; j < S; j++)
            if (cl[j] == i) list[m++] = j;
        mcnt = m;
    }
    __syncthreads();
    const int m = mcnt;

    const float4* base = (const float4*)(pa + (size_t)b * S * N);
    float4 a0 = make_float4(EPS, EPS, EPS, EPS);
    float4 a1 = a0;

    if (m > 0) {
        // Software-pipelined: always have the next row's loads in flight.
        const float4* row = base + (size_t)list[0] * (N / 4);
        float4 p0 = __ldcs(row + t);
        float4 p1 = __ldcs(row + t + 1024);
        for (int r = 1; r < m; r++) {
            const float4* nrow = base + (size_t)list[r] * (N / 4);
            float4 q0 = __ldcs(nrow + t);
            float4 q1 = __ldcs(nrow + t + 1024);
            a0.x += p0.x; a0.y += p0.y; a0.z += p0.z; a0.w += p0.w;
            a1.x += p1.x; a1.y += p1.y; a1.z += p1.z; a1.w += p1.w;
            p0 = q0; p1 = q1;
        }
        a0.x += p0.x; a0.y += p0.y; a0.z += p0.z; a0.w += p0.w;
        a1.x += p1.x; a1.y += p1.y; a1.z += p1.z; a1.w += p1.w;
    }

    // Block reduction for the row normalizer
    float ls = (a0.x + a0.y) + (a0.z + a0.w) + (a1.x + a1.y) + (a1.z + a1.w);
    #pragma unroll
    for (int off = 16; off > 0; off >>= 1)
        ls += __shfl_xor_sync(0xFFFFFFFFu, ls, off);
    int warp = t >> 5, lane = t & 31;
    if (lane == 0) wsum[warp] = ls;
    __syncthreads();
    if (warp == 0) {
        float v = wsum[lane];  // exactly 32 warps
        #pragma unroll
        for (int off = 16; off > 0; off >>= 1)
            v += __shfl_xor_sync(0xFFFFFFFFu, v, off);
        if (lane == 0) wsum[0] = v;
    }
    __syncthreads();
    const float inv = 1.0f / wsum[0];

    float4* o = (float4*)(out_attn + (size_t)(b * S + i) * N);
    float4 r0 = make_float4(a0.x * inv, a0.y * inv, a0.z * inv, a0.w * inv);
    float4 r1 = make_float4(a1.x * inv, a1.y * inv, a1.z * inv, a1.w * inv);
    __stcs(o + t, r0);
    __stcs(o + t + 1024, r1);
}

// ---------------------------------------------------------------------------
extern "C" void kernel_launch(void* const* d_in, const int* in_sizes, int n_in,
                              void* d_out, int out_size)
{
    const float* slots    = (const float*)d_in[0];   // [B,S,D]
    const float* pa       = (const float*)d_in[1];   // [B,S,N]
    const int*   clusters = (const int*)d_in[2];     // [B,S] int32

    float* out = (float*)d_out;
    float* out_slots = out;                              // [B,S,D]
    float* out_attn  = out + (size_t)B * S * D;          // [B,S,N]
    float* out_nums  = out_attn + (size_t)B * S * N;     // [B]

    fused_kernel<<<dim3(S + 1, B), 1024>>>(slots, pa, clusters,
                                           out_slots, out_attn, out_nums);
}

// round 4
// speedup vs baseline: 1.6015x; 1.6015x over previous
#include <cuda_runtime.h>

#define EPS 1e-8f

namespace {
constexpr int B = 256;
constexpr int S = 24;
constexpr int D = 256;
constexpr int N = 8192;
constexpr int T = 512;           // threads per block
constexpr int F4 = N / 4 / T;    // float4s per thread = 4
}

// ---------------------------------------------------------------------------
// Fused kernel: grid = (S+1, B), 512 threads, >=3 blocks/SM enforced.
//   blockIdx.x == i in [0,S): output row (b,i) of new_patch_attn.
//   blockIdx.x == S:          new_slots + slot_nums for batch b (smem-based,
//                             no register arrays -> cannot inflate regs).
// ---------------------------------------------------------------------------
__global__ void __launch_bounds__(T, 3) fused_kernel(
    const float* __restrict__ slots,     // [B,S,D]
    const float* __restrict__ pa,        // [B,S,N]
    const int* __restrict__ clusters,    // [B,S] int32
    float* __restrict__ out_slots,       // [B,S,D]
    float* __restrict__ out_attn,        // [B,S,N]
    float* __restrict__ out_nums)        // [B]
{
    const int i = blockIdx.x;
    const int b = blockIdx.y;
    const int t = threadIdx.x;

    __shared__ int   cls[S];
    __shared__ int   list[S];
    __shared__ int   mcnt;
    __shared__ float wsum[T / 32];
    __shared__ float stile[S * D];   // 24KB, used only by the slots path

    // ------------------------------------------------------------------
    // Slots path: one block per batch. All state lives in smem.
    // ------------------------------------------------------------------
    if (i == S) {
        if (t < S) cls[t] = clusters[b * S + t];
        for (int idx = t; idx < S * D; idx += T)
            stile[idx] = slots[(size_t)b * S * D + idx];
        __syncthreads();

        if (t < D) {
            const int d = t;
            float* ob = out_slots + (size_t)b * S * D + d;
            #pragma unroll
            for (int ii = 0; ii < S; ii++) {
                float acc = 0.0f;
                int c = 0;
                #pragma unroll
                for (int j = 0; j < S; j++) {
                    bool hit = (cls[j] == ii);
                    if (hit) acc += stile[j * D + d];
                    c += hit;
                }
                ob[ii * D] = acc / ((float)c + EPS);
            }
            if (d == 0) {
                int n = 0;
                #pragma unroll
                for (int ii = 0; ii < S; ii++) {
                    int c = 0;
                    #pragma unroll
                    for (int j = 0; j < S; j++) c += (cls[j] == ii);
                    n += (c > 0);
                }
                out_nums[b] = (float)n;
            }
        }
        return;
    }

    // ------------------------------------------------------------------
    // Attn path: segment-sum + EPS + row-normalize for output row (b,i)
    // ------------------------------------------------------------------
    if (t == 0) {
        int m = 0;
        #pragma unroll
        for (int j = 0; j < S; j++) {
            int c = clusters[b * S + j];
            if (c == i) list[m++] = j;
        }
        mcnt = m;
    }
    __syncthreads();
    const int m = mcnt;

    const float4* base = (const float4*)(pa + (size_t)b * S * N);

    float4 acc[F4];
    #pragma unroll
    for (int k = 0; k < F4; k++) acc[k] = make_float4(EPS, EPS, EPS, EPS);

    if (m > 0) {
        // Software pipeline across member rows: 4 loads always in flight.
        float4 pre[F4];
        {
            const float4* row = base + (size_t)list[0] * (N / 4);
            #pragma unroll
            for (int k = 0; k < F4; k++) pre[k] = __ldcs(row + t + k * T);
        }
        for (int r = 1; r < m; r++) {
            const float4* row = base + (size_t)list[r] * (N / 4);
            float4 nxt[F4];
            #pragma unroll
            for (int k = 0; k < F4; k++) nxt[k] = __ldcs(row + t + k * T);
            #pragma unroll
            for (int k = 0; k < F4; k++) {
                acc[k].x += pre[k].x; acc[k].y += pre[k].y;
                acc[k].z += pre[k].z; acc[k].w += pre[k].w;
                pre[k] = nxt[k];
            }
        }
        #pragma unroll
        for (int k = 0; k < F4; k++) {
            acc[k].x += pre[k].x; acc[k].y += pre[k].y;
            acc[k].z += pre[k].z; acc[k].w += pre[k].w;
        }
    }

    // Row normalizer: warp partials -> smem -> every thread sums 16 partials.
    float ls = 0.0f;
    #pragma unroll
    for (int k = 0; k < F4; k++)
        ls += (acc[k].x + acc[k].y) + (acc[k].z + acc[k].w);
    #pragma unroll
    for (int off = 16; off > 0; off >>= 1)
        ls += __shfl_xor_sync(0xFFFFFFFFu, ls, off);
    if ((t & 31) == 0) wsum[t >> 5] = ls;
    __syncthreads();

    float tot = 0.0f;
    #pragma unroll
    for (int k = 0; k < T / 32; k++) tot += wsum[k];   // broadcast reads
    const float inv = 1.0f / tot;

    float4* o = (float4*)(out_attn + (size_t)(b * S + i) * N);
    #pragma unroll
    for (int k = 0; k < F4; k++) {
        float4 r = make_float4(acc[k].x * inv, acc[k].y * inv,
                               acc[k].z * inv, acc[k].w * inv);
        __stcs(o + t + k * T, r);
    }
}

// ---------------------------------------------------------------------------
extern "C" void kernel_launch(void* const* d_in, const int* in_sizes, int n_in,
                              void* d_out, int out_size)
{
    const float* slots    = (const float*)d_in[0];   // [B,S,D]
    const float* pa       = (const float*)d_in[1];   // [B,S,N]
    const int*   clusters = (const int*)d_in[2];     // [B,S] int32

    float* out = (float*)d_out;
    float* out_slots = out;                              // [B,S,D]
    float* out_attn  = out + (size_t)B * S * D;          // [B,S,N]
    float* out_nums  = out_attn + (size_t)B * S * N;     // [B]

    fused_kernel<<<dim3(S + 1, B), T>>>(slots, pa, clusters,
                                        out_slots, out_attn, out_nums);
}